// round 1
// baseline (speedup 1.0000x reference)
#include <cuda_runtime.h>

#define TSEQ   2048
#define MTOT   4096          // B*T
#define QKROW  1536          // q(1024) | k(256) | v(256)
#define NHEAD  16
#define NKV    4
#define HD     64

// Scratch (no allocation allowed): qkv activations and attention output.
__device__ float g_qkv[(size_t)MTOT * QKROW];
__device__ float g_y[(size_t)MTOT * 1024];

// ---------------------------------------------------------------------------
// SGEMM: C[m][coff+n] = sum_k A[m][k] * B[n][k]   (A: MxK row-major, B: NxK)
// 128x128 block, BK=16, 256 threads, 8x8 per-thread micro-tile.
// srcsel: 0 -> Aext, 1 -> g_y.  dstsel: 0 -> g_qkv, 1 -> Cext.
// ---------------------------------------------------------------------------
__global__ __launch_bounds__(256)
void sgemm_tn(const float* __restrict__ Aext, const float* __restrict__ B,
              float* __restrict__ Cext, int K, int ldc, int coff,
              int srcsel, int dstsel)
{
    const float* A = srcsel ? g_y : Aext;
    float* C = dstsel ? Cext : g_qkv;

    __shared__ float As[16][128];
    __shared__ float Bs[16][128];

    const int tid = threadIdx.x;
    const int bm = blockIdx.y << 7;
    const int bn = blockIdx.x << 7;
    const int lr = tid >> 2;          // 0..63
    const int lc = (tid & 3) << 2;    // 0,4,8,12
    const float* Ag = A + (size_t)(bm + lr) * K + lc;
    const float* Bg = B + (size_t)(bn + lr) * K + lc;
    const int tr = tid >> 4;          // 0..15 (m sub-block)
    const int tc = tid & 15;          // 0..15 (n sub-block)

    float acc[8][8];
    #pragma unroll
    for (int i = 0; i < 8; i++)
        #pragma unroll
        for (int j = 0; j < 8; j++) acc[i][j] = 0.f;

    for (int kt = 0; kt < K; kt += 16) {
        float4 a0 = *(const float4*)(Ag + kt);
        float4 a1 = *(const float4*)(Ag + (size_t)64 * K + kt);
        float4 b0 = *(const float4*)(Bg + kt);
        float4 b1 = *(const float4*)(Bg + (size_t)64 * K + kt);
        __syncthreads();
        As[lc+0][lr] = a0.x; As[lc+1][lr] = a0.y; As[lc+2][lr] = a0.z; As[lc+3][lr] = a0.w;
        As[lc+0][lr+64] = a1.x; As[lc+1][lr+64] = a1.y; As[lc+2][lr+64] = a1.z; As[lc+3][lr+64] = a1.w;
        Bs[lc+0][lr] = b0.x; Bs[lc+1][lr] = b0.y; Bs[lc+2][lr] = b0.z; Bs[lc+3][lr] = b0.w;
        Bs[lc+0][lr+64] = b1.x; Bs[lc+1][lr+64] = b1.y; Bs[lc+2][lr+64] = b1.z; Bs[lc+3][lr+64] = b1.w;
        __syncthreads();
        #pragma unroll
        for (int k = 0; k < 16; k++) {
            float rm[8], rn[8];
            *(float4*)&rm[0] = *(const float4*)&As[k][tr*8];
            *(float4*)&rm[4] = *(const float4*)&As[k][tr*8+4];
            *(float4*)&rn[0] = *(const float4*)&Bs[k][tc*8];
            *(float4*)&rn[4] = *(const float4*)&Bs[k][tc*8+4];
            #pragma unroll
            for (int i = 0; i < 8; i++)
                #pragma unroll
                for (int j = 0; j < 8; j++)
                    acc[i][j] += rm[i] * rn[j];
        }
    }
    #pragma unroll
    for (int i = 0; i < 8; i++) {
        float* cp = C + (size_t)(bm + tr*8 + i) * ldc + coff + bn + tc*8;
        *(float4*)cp     = make_float4(acc[i][0], acc[i][1], acc[i][2], acc[i][3]);
        *(float4*)(cp+4) = make_float4(acc[i][4], acc[i][5], acc[i][6], acc[i][7]);
    }
}

// ---------------------------------------------------------------------------
// Post-process: per token (block), 24 warps:
//   warps 0..15 : q head h  -> rotary -> rmsnorm -> *1.2  (in place)
//   warps 16..19: k head    -> rotary -> rmsnorm -> *1.2  (in place)
//   warps 20..23: v head    -> v += 3*sigmoid(x[:12]@Wg[kv]) * ve
// ---------------------------------------------------------------------------
__global__ __launch_bounds__(768)
void postproc(const float* __restrict__ x, const float* __restrict__ ve,
              const float* __restrict__ cs, const float* __restrict__ sn,
              const float* __restrict__ Wg)
{
    const int row = blockIdx.x;            // b*T + t
    const int t = row & (TSEQ - 1);
    const int w = threadIdx.x >> 5;
    const int l = threadIdx.x & 31;
    float* base = g_qkv + (size_t)row * QKROW;

    if (w < 20) {
        const int off = (w < 16) ? (w << 6) : (1024 + ((w - 16) << 6));
        float x1 = base[off + l];
        float x2 = base[off + 32 + l];
        float c = cs[t * 32 + l];
        float s = sn[t * 32 + l];
        float a  = x1 * c + x2 * s;
        float bb = x2 * c - x1 * s;
        float ss = a * a + bb * bb;
        #pragma unroll
        for (int d = 16; d >= 1; d >>= 1) ss += __shfl_xor_sync(0xffffffffu, ss, d);
        float r = rsqrtf(ss * (1.0f / 64.0f) + 1.1920929e-7f) * 1.2f;
        base[off + l]      = a  * r;
        base[off + 32 + l] = bb * r;
    } else {
        const int kv = w - 20;
        float dot = (l < 12) ? x[(size_t)row * 1024 + l] * Wg[kv * 12 + l] : 0.f;
        #pragma unroll
        for (int d = 16; d >= 1; d >>= 1) dot += __shfl_xor_sync(0xffffffffu, dot, d);
        float g = 3.0f / (1.0f + __expf(-dot));
        const int off = 1280 + (kv << 6);
        const float* vep = ve + (size_t)row * 256 + (kv << 6);
        base[off + l]      += g * vep[l];
        base[off + 32 + l] += g * vep[32 + l];
    }
}

// ---------------------------------------------------------------------------
// Flash attention, fp32. Block = (qtile 64, head, batch), 256 threads.
// smem: Q[64x64], KP[64x64] (K stored d-major, reused as P after QK^T), V[64x64].
// Exactly 48 KB static smem.
// ---------------------------------------------------------------------------
__global__ __launch_bounds__(256)
void attn(const int* __restrict__ wlp)
{
    __shared__ float Qs[64 * 64];   // [q][d]
    __shared__ float KP[64 * 64];   // [d][k] for K, then [q][k] for P
    __shared__ float Vs[64 * 64];   // [k][d]

    const int tid = threadIdx.x;
    const int qt = blockIdx.x;      // 0..31
    const int h  = blockIdx.y;      // 0..15
    const int b  = blockIdx.z;      // 0..1
    const int window = *wlp;
    const int kv = h >> 2;
    const int q0 = qt << 6;

    const float* rowbase = g_qkv + (size_t)b * TSEQ * QKROW;
    const float* qptr = rowbase + h * 64;
    const float* kptr = rowbase + 1024 + kv * 64;
    const float* vptr = rowbase + 1280 + kv * 64;

    {   // load Q tile
        const int r = tid >> 2;
        const int c = (tid & 3) << 4;
        const float* src = qptr + (size_t)(q0 + r) * QKROW + c;
        #pragma unroll
        for (int i = 0; i < 16; i += 4)
            *(float4*)&Qs[r * 64 + c + i] = *(const float4*)(src + i);
    }

    const int tr = tid >> 4;   // q row group (4 rows)
    const int tc = tid & 15;   // col group (4 cols)

    float o[4][4];
    float m[4], l[4];
    #pragma unroll
    for (int i = 0; i < 4; i++) {
        m[i] = -1e30f; l[i] = 0.f;
        #pragma unroll
        for (int j = 0; j < 4; j++) o[i][j] = 0.f;
    }

    int lo = q0 - window; if (lo < 0) lo = 0;
    const int kt0 = lo >> 6;

    for (int kt = kt0; kt <= qt; kt++) {
        const int k0 = kt << 6;
        __syncthreads();   // prev-iteration P/V readers done
        {   // load K (transposed to d-major) and V
            const int r = tid >> 2;
            const int c = (tid & 3) << 4;
            const float* ks = kptr + (size_t)(k0 + r) * QKROW + c;
            const float* vs = vptr + (size_t)(k0 + r) * QKROW + c;
            #pragma unroll
            for (int i = 0; i < 16; i += 4) {
                float4 kk4 = *(const float4*)(ks + i);
                KP[(c + i    ) * 64 + r] = kk4.x;
                KP[(c + i + 1) * 64 + r] = kk4.y;
                KP[(c + i + 2) * 64 + r] = kk4.z;
                KP[(c + i + 3) * 64 + r] = kk4.w;
                *(float4*)&Vs[r * 64 + c + i] = *(const float4*)(vs + i);
            }
        }
        __syncthreads();

        // S = Q K^T  (4x4 per thread)
        float s[4][4];
        #pragma unroll
        for (int i = 0; i < 4; i++)
            #pragma unroll
            for (int j = 0; j < 4; j++) s[i][j] = 0.f;
        #pragma unroll 16
        for (int kk = 0; kk < 64; kk++) {
            float ra0 = Qs[(tr * 4 + 0) * 64 + kk];
            float ra1 = Qs[(tr * 4 + 1) * 64 + kk];
            float ra2 = Qs[(tr * 4 + 2) * 64 + kk];
            float ra3 = Qs[(tr * 4 + 3) * 64 + kk];
            float4 rb = *(const float4*)&KP[kk * 64 + tc * 4];
            s[0][0] += ra0 * rb.x; s[0][1] += ra0 * rb.y; s[0][2] += ra0 * rb.z; s[0][3] += ra0 * rb.w;
            s[1][0] += ra1 * rb.x; s[1][1] += ra1 * rb.y; s[1][2] += ra1 * rb.z; s[1][3] += ra1 * rb.w;
            s[2][0] += ra2 * rb.x; s[2][1] += ra2 * rb.y; s[2][2] += ra2 * rb.z; s[2][3] += ra2 * rb.w;
            s[3][0] += ra3 * rb.x; s[3][1] += ra3 * rb.y; s[3][2] += ra3 * rb.z; s[3][3] += ra3 * rb.w;
        }
        __syncthreads();   // done reading K from KP; safe to overwrite with P

        // mask + online softmax (row stats via 16-lane xor-shuffles)
        #pragma unroll
        for (int i = 0; i < 4; i++) {
            const int qi = q0 + tr * 4 + i;
            #pragma unroll
            for (int j = 0; j < 4; j++) {
                const int kj = k0 + tc * 4 + j;
                const bool ok = (kj <= qi) && (qi - kj <= window);
                s[i][j] = ok ? s[i][j] * 0.125f : -1e30f;
            }
            float rmax = fmaxf(fmaxf(s[i][0], s[i][1]), fmaxf(s[i][2], s[i][3]));
            #pragma unroll
            for (int d = 8; d >= 1; d >>= 1)
                rmax = fmaxf(rmax, __shfl_xor_sync(0xffffffffu, rmax, d));
            const float mnew = fmaxf(m[i], rmax);
            const float corr = __expf(m[i] - mnew);
            float rsum = 0.f;
            #pragma unroll
            for (int j = 0; j < 4; j++) {
                s[i][j] = __expf(s[i][j] - mnew);
                rsum += s[i][j];
            }
            #pragma unroll
            for (int d = 8; d >= 1; d >>= 1)
                rsum += __shfl_xor_sync(0xffffffffu, rsum, d);
            m[i] = mnew;
            l[i] = l[i] * corr + rsum;
            #pragma unroll
            for (int j = 0; j < 4; j++) o[i][j] *= corr;
            *(float4*)&KP[(tr * 4 + i) * 64 + tc * 4] =
                make_float4(s[i][0], s[i][1], s[i][2], s[i][3]);
        }
        __syncthreads();   // P visible

        // O += P V  (o cols are d)
        #pragma unroll 16
        for (int kk = 0; kk < 64; kk++) {
            float pa0 = KP[(tr * 4 + 0) * 64 + kk];
            float pa1 = KP[(tr * 4 + 1) * 64 + kk];
            float pa2 = KP[(tr * 4 + 2) * 64 + kk];
            float pa3 = KP[(tr * 4 + 3) * 64 + kk];
            float4 vb = *(const float4*)&Vs[kk * 64 + tc * 4];
            o[0][0] += pa0 * vb.x; o[0][1] += pa0 * vb.y; o[0][2] += pa0 * vb.z; o[0][3] += pa0 * vb.w;
            o[1][0] += pa1 * vb.x; o[1][1] += pa1 * vb.y; o[1][2] += pa1 * vb.z; o[1][3] += pa1 * vb.w;
            o[2][0] += pa2 * vb.x; o[2][1] += pa2 * vb.y; o[2][2] += pa2 * vb.z; o[2][3] += pa2 * vb.w;
            o[3][0] += pa3 * vb.x; o[3][1] += pa3 * vb.y; o[3][2] += pa3 * vb.z; o[3][3] += pa3 * vb.w;
        }
    }

    #pragma unroll
    for (int i = 0; i < 4; i++) {
        const float inv = 1.0f / l[i];
        float* yp = g_y + (size_t)(b * TSEQ + q0 + tr * 4 + i) * 1024 + h * 64 + tc * 4;
        *(float4*)yp = make_float4(o[i][0] * inv, o[i][1] * inv, o[i][2] * inv, o[i][3] * inv);
    }
}

// ---------------------------------------------------------------------------
extern "C" void kernel_launch(void* const* d_in, const int* in_sizes, int n_in,
                              void* d_out, int out_size)
{
    const float* x  = (const float*)d_in[0];
    const float* ve = (const float*)d_in[1];
    const float* cs = (const float*)d_in[2];
    const float* sn = (const float*)d_in[3];
    const float* Wq = (const float*)d_in[4];
    const float* Wk = (const float*)d_in[5];
    const float* Wv = (const float*)d_in[6];
    const float* Wo = (const float*)d_in[7];
    const float* Wg = (const float*)d_in[8];
    const int*   wl = (const int*)d_in[9];
    float* out = (float*)d_out;

    // QKV projections -> g_qkv rows [q(1024) | k(256) | v(256)]
    sgemm_tn<<<dim3(8, 32), 256>>>(x, Wq, nullptr, 1024, QKROW, 0,    0, 0);
    sgemm_tn<<<dim3(2, 32), 256>>>(x, Wk, nullptr, 1024, QKROW, 1024, 0, 0);
    sgemm_tn<<<dim3(2, 32), 256>>>(x, Wv, nullptr, 1024, QKROW, 1280, 0, 0);

    // gate*ve add, rotary + rmsnorm * QK_SCALE
    postproc<<<MTOT, 768>>>(x, ve, cs, sn, Wg);

    // sliding-window flash attention -> g_y
    attn<<<dim3(32, NHEAD, 2), 256>>>(wl);

    // output projection: out = g_y @ Wo^T
    sgemm_tn<<<dim3(8, 32), 256>>>(nullptr, Wo, out, 1024, 1024, 0, 1, 1);
}

// round 7
// speedup vs baseline: 2.0121x; 2.0121x over previous
#include <cuda_runtime.h>
#include <cstdint>

#define TSEQ   2048
#define MTOT   4096          // B*T
#define QKROW  1536          // q(1024) | k(256) | v(256)
#define NHEAD  16
#define NKV    4
#define HD     64

// Scratch (no allocation allowed): qkv activations and attention output.
__device__ float g_qkv[(size_t)MTOT * QKROW];
__device__ float g_y[(size_t)MTOT * 1024];

__device__ __forceinline__ float tf32r(float x) {
    uint32_t u;
    asm("cvt.rna.tf32.f32 %0, %1;" : "=r"(u) : "f"(x));
    return __uint_as_float(u);
}

__device__ __forceinline__ void mma_tf32(float* d, const uint32_t* a, const uint32_t* b) {
    asm volatile(
        "mma.sync.aligned.m16n8k8.row.col.f32.tf32.tf32.f32 "
        "{%0,%1,%2,%3}, {%4,%5,%6,%7}, {%8,%9}, {%0,%1,%2,%3};\n"
        : "+f"(d[0]), "+f"(d[1]), "+f"(d[2]), "+f"(d[3])
        : "r"(a[0]), "r"(a[1]), "r"(a[2]), "r"(a[3]), "r"(b[0]), "r"(b[1]));
}

// ---------------------------------------------------------------------------
// TF32 tensor-core GEMM: C[m][coff+n] = sum_k A[m][k] * B[n][k]
// Block 128x128, BK=32, 256 threads = 8 warps (2m x 4n), warp tile 64x32.
// srcsel: 0 -> Aext, 1 -> g_y.  dstsel: 0 -> g_qkv, 1 -> Cext.
// ---------------------------------------------------------------------------
__global__ __launch_bounds__(256)
void gemm_tf32(const float* __restrict__ Aext, const float* __restrict__ B,
               float* __restrict__ Cext, int K, int ldc, int coff,
               int srcsel, int dstsel)
{
    const float* A = srcsel ? g_y : Aext;
    float* C = dstsel ? Cext : g_qkv;

    __shared__ float As[32][132];   // [k][m], padded
    __shared__ float Bs[32][132];   // [k][n], padded

    const int tid   = threadIdx.x;
    const int bm    = blockIdx.y << 7;
    const int bn    = blockIdx.x << 7;
    const int wid   = tid >> 5;
    const int lane  = tid & 31;
    const int group = lane >> 2;    // 0..7
    const int qid   = lane & 3;     // 0..3
    const int wm    = (wid >> 2) << 6;  // 0 or 64
    const int wn    = (wid & 3) << 5;   // 0,32,64,96

    float acc[4][4][4];
    #pragma unroll
    for (int mt = 0; mt < 4; mt++)
        #pragma unroll
        for (int nt = 0; nt < 4; nt++)
            #pragma unroll
            for (int r = 0; r < 4; r++) acc[mt][nt][r] = 0.f;

    for (int kt = 0; kt < K; kt += 32) {
        __syncthreads();
        #pragma unroll
        for (int it = 0; it < 4; it++) {
            const int idx = tid + (it << 8);
            const int r   = idx >> 3;          // 0..127
            const int c4  = (idx & 7) << 2;    // 0,4,...,28
            float4 av = *(const float4*)(A + (size_t)(bm + r) * K + kt + c4);
            float4 bv = *(const float4*)(B + (size_t)(bn + r) * K + kt + c4);
            As[c4+0][r] = tf32r(av.x); As[c4+1][r] = tf32r(av.y);
            As[c4+2][r] = tf32r(av.z); As[c4+3][r] = tf32r(av.w);
            Bs[c4+0][r] = tf32r(bv.x); Bs[c4+1][r] = tf32r(bv.y);
            Bs[c4+2][r] = tf32r(bv.z); Bs[c4+3][r] = tf32r(bv.w);
        }
        __syncthreads();

        #pragma unroll
        for (int kk = 0; kk < 32; kk += 8) {
            uint32_t af[4][4], bf[4][2];
            #pragma unroll
            for (int mt = 0; mt < 4; mt++) {
                const int m0 = wm + (mt << 4) + group;
                af[mt][0] = __float_as_uint(As[kk + qid    ][m0]);
                af[mt][1] = __float_as_uint(As[kk + qid    ][m0 + 8]);
                af[mt][2] = __float_as_uint(As[kk + qid + 4][m0]);
                af[mt][3] = __float_as_uint(As[kk + qid + 4][m0 + 8]);
            }
            #pragma unroll
            for (int nt = 0; nt < 4; nt++) {
                const int n0 = wn + (nt << 3) + group;
                bf[nt][0] = __float_as_uint(Bs[kk + qid    ][n0]);
                bf[nt][1] = __float_as_uint(Bs[kk + qid + 4][n0]);
            }
            #pragma unroll
            for (int mt = 0; mt < 4; mt++)
                #pragma unroll
                for (int nt = 0; nt < 4; nt++)
                    mma_tf32(acc[mt][nt], af[mt], bf[nt]);
        }
    }

    #pragma unroll
    for (int mt = 0; mt < 4; mt++) {
        const int r0 = bm + wm + (mt << 4) + group;
        #pragma unroll
        for (int nt = 0; nt < 4; nt++) {
            const int c0 = coff + bn + wn + (nt << 3) + (qid << 1);
            *(float2*)&C[(size_t)r0 * ldc + c0] =
                make_float2(acc[mt][nt][0], acc[mt][nt][1]);
            *(float2*)&C[(size_t)(r0 + 8) * ldc + c0] =
                make_float2(acc[mt][nt][2], acc[mt][nt][3]);
        }
    }
}

// ---------------------------------------------------------------------------
// Post-process (rotary+rmsnorm on q/k, gated ve add on v).
// ---------------------------------------------------------------------------
__global__ __launch_bounds__(768)
void postproc(const float* __restrict__ x, const float* __restrict__ ve,
              const float* __restrict__ cs, const float* __restrict__ sn,
              const float* __restrict__ Wg)
{
    const int row = blockIdx.x;            // b*T + t
    const int t = row & (TSEQ - 1);
    const int w = threadIdx.x >> 5;
    const int l = threadIdx.x & 31;
    float* base = g_qkv + (size_t)row * QKROW;

    if (w < 20) {
        const int off = (w < 16) ? (w << 6) : (1024 + ((w - 16) << 6));
        float x1 = base[off + l];
        float x2 = base[off + 32 + l];
        float c = cs[t * 32 + l];
        float s = sn[t * 32 + l];
        float a  = x1 * c + x2 * s;
        float bb = x2 * c - x1 * s;
        float ss = a * a + bb * bb;
        #pragma unroll
        for (int d = 16; d >= 1; d >>= 1) ss += __shfl_xor_sync(0xffffffffu, ss, d);
        float r = rsqrtf(ss * (1.0f / 64.0f) + 1.1920929e-7f) * 1.2f;
        base[off + l]      = a  * r;
        base[off + 32 + l] = bb * r;
    } else {
        const int kv = w - 20;
        float dot = (l < 12) ? x[(size_t)row * 1024 + l] * Wg[kv * 12 + l] : 0.f;
        #pragma unroll
        for (int d = 16; d >= 1; d >>= 1) dot += __shfl_xor_sync(0xffffffffu, dot, d);
        float g = 3.0f / (1.0f + __expf(-dot));
        const int off = 1280 + (kv << 6);
        const float* vep = ve + (size_t)row * 256 + (kv << 6);
        base[off + l]      += g * vep[l];
        base[off + 32 + l] += g * vep[32 + l];
    }
}

// ---------------------------------------------------------------------------
// Flash attention on TF32 tensor cores.
// Block = (qtile 128, head, batch), 256 threads = 8 warps; warp w owns q rows
// [w*16, w*16+16) and the full 64-key width -> softmax is warp-local.
// smem (dynamic, 105472 B):
//   Qs[128][68]  q rows (tf32)              34816 B
//   Ks[64][68]   keys, natural [kcol][d]    17408 B
//   Vs[64][72]   values, natural [k][d]     18432 B
//   Ps[128][68]  exp(scores), per-warp rows 34816 B
// Fragment maps (m16n8k8 tf32): A(g,qid)/(g+8,qid)/(g,qid+4)/(g+8,qid+4);
// B(qid,g)/(qid+4,g); C rows g,g+8 cols 2qid,2qid+1.
// ---------------------------------------------------------------------------
#define PADQ 68
#define PADK 68
#define PADV 72
#define OFF_K (128 * PADQ)
#define OFF_V (OFF_K + 64 * PADK)
#define OFF_P (OFF_V + 64 * PADV)
#define SM_FLOATS (OFF_P + 128 * PADQ)

__global__ __launch_bounds__(256)
void attn(const int* __restrict__ wlp)
{
    extern __shared__ float sm[];
    float* Qs = sm;
    float* Ks = sm + OFF_K;
    float* Vs = sm + OFF_V;
    float* Ps = sm + OFF_P;

    const int tid  = threadIdx.x;
    const int w    = tid >> 5;
    const int lane = tid & 31;
    const int g    = lane >> 2;
    const int qid  = lane & 3;
    const int qt = blockIdx.x;      // 0..15
    const int h  = blockIdx.y;      // 0..15
    const int b  = blockIdx.z;      // 0..1
    const int window = *wlp;
    const int kv = h >> 2;
    const int q0 = qt << 7;

    const float* rowbase = g_qkv + (size_t)b * TSEQ * QKROW;
    const float* qptr = rowbase + h * 64;
    const float* kptr = rowbase + 1024 + kv * 64;
    const float* vptr = rowbase + 1280 + kv * 64;

    {   // load Q tile (128 x 64), tf32-rounded
        const int r = tid >> 1;
        const int c0 = (tid & 1) << 5;
        const float* src = qptr + (size_t)(q0 + r) * QKROW + c0;
        float* dst = Qs + r * PADQ + c0;
        #pragma unroll
        for (int i = 0; i < 32; i += 4) {
            float4 v4 = *(const float4*)(src + i);
            dst[i+0] = tf32r(v4.x); dst[i+1] = tf32r(v4.y);
            dst[i+2] = tf32r(v4.z); dst[i+3] = tf32r(v4.w);
        }
    }

    const int mrow = (w << 4) + g;        // this thread's low row within tile
    const int qlo = q0 + mrow;
    const int qhi = qlo + 8;

    float o[8][4];
    #pragma unroll
    for (int nt = 0; nt < 8; nt++)
        #pragma unroll
        for (int r = 0; r < 4; r++) o[nt][r] = 0.f;
    float m_lo = -1e30f, m_hi = -1e30f, l_lo = 0.f, l_hi = 0.f;

    int lo = q0 - window; if (lo < 0) lo = 0;
    const int kt0 = lo >> 6;
    const int ktmax = (q0 + 127) >> 6;

    for (int kt = kt0; kt <= ktmax; kt++) {
        const int k0 = kt << 6;
        __syncthreads();
        {   // load K, V (64 x 64 each), natural layout, tf32-rounded
            const int r = tid >> 2;
            const int c0 = (tid & 3) << 4;
            const float* ks = kptr + (size_t)(k0 + r) * QKROW + c0;
            const float* vs = vptr + (size_t)(k0 + r) * QKROW + c0;
            float* kd = Ks + r * PADK + c0;
            float* vd = Vs + r * PADV + c0;
            #pragma unroll
            for (int i = 0; i < 16; i += 4) {
                float4 k4 = *(const float4*)(ks + i);
                float4 v4 = *(const float4*)(vs + i);
                kd[i+0] = tf32r(k4.x); kd[i+1] = tf32r(k4.y);
                kd[i+2] = tf32r(k4.z); kd[i+3] = tf32r(k4.w);
                vd[i+0] = tf32r(v4.x); vd[i+1] = tf32r(v4.y);
                vd[i+2] = tf32r(v4.z); vd[i+3] = tf32r(v4.w);
            }
        }
        __syncthreads();

        // ---- S = Q K^T (16 x 64 per warp) ----
        float s[8][4];
        #pragma unroll
        for (int nt = 0; nt < 8; nt++)
            #pragma unroll
            for (int r = 0; r < 4; r++) s[nt][r] = 0.f;
        #pragma unroll
        for (int kk = 0; kk < 64; kk += 8) {
            uint32_t a[4];
            a[0] = __float_as_uint(Qs[(mrow    ) * PADQ + kk + qid]);
            a[1] = __float_as_uint(Qs[(mrow + 8) * PADQ + kk + qid]);
            a[2] = __float_as_uint(Qs[(mrow    ) * PADQ + kk + qid + 4]);
            a[3] = __float_as_uint(Qs[(mrow + 8) * PADQ + kk + qid + 4]);
            #pragma unroll
            for (int nt = 0; nt < 8; nt++) {
                uint32_t bfr[2];
                bfr[0] = __float_as_uint(Ks[((nt << 3) + g) * PADK + kk + qid]);
                bfr[1] = __float_as_uint(Ks[((nt << 3) + g) * PADK + kk + qid + 4]);
                mma_tf32(s[nt], a, bfr);
            }
        }

        // ---- mask + online softmax (warp-local rows) ----
        float rx_lo = -1e30f, rx_hi = -1e30f;
        #pragma unroll
        for (int nt = 0; nt < 8; nt++) {
            #pragma unroll
            for (int c = 0; c < 2; c++) {
                const int kj = k0 + (nt << 3) + (qid << 1) + c;
                const bool ok_lo = (kj <= qlo) && (qlo - kj <= window);
                const bool ok_hi = (kj <= qhi) && (qhi - kj <= window);
                s[nt][c]     = ok_lo ? s[nt][c]     * 0.125f : -1e30f;
                s[nt][2 + c] = ok_hi ? s[nt][2 + c] * 0.125f : -1e30f;
                rx_lo = fmaxf(rx_lo, s[nt][c]);
                rx_hi = fmaxf(rx_hi, s[nt][2 + c]);
            }
        }
        rx_lo = fmaxf(rx_lo, __shfl_xor_sync(0xffffffffu, rx_lo, 1));
        rx_lo = fmaxf(rx_lo, __shfl_xor_sync(0xffffffffu, rx_lo, 2));
        rx_hi = fmaxf(rx_hi, __shfl_xor_sync(0xffffffffu, rx_hi, 1));
        rx_hi = fmaxf(rx_hi, __shfl_xor_sync(0xffffffffu, rx_hi, 2));

        const float mn_lo = fmaxf(m_lo, rx_lo);
        const float mn_hi = fmaxf(m_hi, rx_hi);
        const float cr_lo = __expf(m_lo - mn_lo);
        const float cr_hi = __expf(m_hi - mn_hi);
        float rs_lo = 0.f, rs_hi = 0.f;
        #pragma unroll
        for (int nt = 0; nt < 8; nt++) {
            float e0 = __expf(s[nt][0] - mn_lo);
            float e1 = __expf(s[nt][1] - mn_lo);
            float e2 = __expf(s[nt][2] - mn_hi);
            float e3 = __expf(s[nt][3] - mn_hi);
            rs_lo += e0 + e1;
            rs_hi += e2 + e3;
            const int pc = (nt << 3) + (qid << 1);
            *(float2*)&Ps[(mrow    ) * PADQ + pc] = make_float2(tf32r(e0), tf32r(e1));
            *(float2*)&Ps[(mrow + 8) * PADQ + pc] = make_float2(tf32r(e2), tf32r(e3));
        }
        rs_lo += __shfl_xor_sync(0xffffffffu, rs_lo, 1);
        rs_lo += __shfl_xor_sync(0xffffffffu, rs_lo, 2);
        rs_hi += __shfl_xor_sync(0xffffffffu, rs_hi, 1);
        rs_hi += __shfl_xor_sync(0xffffffffu, rs_hi, 2);
        m_lo = mn_lo; m_hi = mn_hi;
        l_lo = l_lo * cr_lo + rs_lo;
        l_hi = l_hi * cr_hi + rs_hi;
        #pragma unroll
        for (int nt = 0; nt < 8; nt++) {
            o[nt][0] *= cr_lo; o[nt][1] *= cr_lo;
            o[nt][2] *= cr_hi; o[nt][3] *= cr_hi;
        }
        __syncwarp();   // P rows visible across own warp's lanes

        // ---- O += P V (16 x 64 per warp) ----
        #pragma unroll
        for (int kk = 0; kk < 64; kk += 8) {
            uint32_t a[4];
            a[0] = __float_as_uint(Ps[(mrow    ) * PADQ + kk + qid]);
            a[1] = __float_as_uint(Ps[(mrow + 8) * PADQ + kk + qid]);
            a[2] = __float_as_uint(Ps[(mrow    ) * PADQ + kk + qid + 4]);
            a[3] = __float_as_uint(Ps[(mrow + 8) * PADQ + kk + qid + 4]);
            #pragma unroll
            for (int nt = 0; nt < 8; nt++) {
                uint32_t bfr[2];
                bfr[0] = __float_as_uint(Vs[(kk + qid    ) * PADV + (nt << 3) + g]);
                bfr[1] = __float_as_uint(Vs[(kk + qid + 4) * PADV + (nt << 3) + g]);
                mma_tf32(o[nt], a, bfr);
            }
        }
        __syncwarp();   // PV reads done before next tile's P overwrite
    }

    const float inv_lo = 1.0f / l_lo;
    const float inv_hi = 1.0f / l_hi;
    float* ylo = g_y + (size_t)(b * TSEQ + qlo) * 1024 + h * 64;
    float* yhi = g_y + (size_t)(b * TSEQ + qhi) * 1024 + h * 64;
    #pragma unroll
    for (int nt = 0; nt < 8; nt++) {
        const int c = (nt << 3) + (qid << 1);
        *(float2*)(ylo + c) = make_float2(o[nt][0] * inv_lo, o[nt][1] * inv_lo);
        *(float2*)(yhi + c) = make_float2(o[nt][2] * inv_hi, o[nt][3] * inv_hi);
    }
}

// ---------------------------------------------------------------------------
extern "C" void kernel_launch(void* const* d_in, const int* in_sizes, int n_in,
                              void* d_out, int out_size)
{
    const float* x  = (const float*)d_in[0];
    const float* ve = (const float*)d_in[1];
    const float* cs = (const float*)d_in[2];
    const float* sn = (const float*)d_in[3];
    const float* Wq = (const float*)d_in[4];
    const float* Wk = (const float*)d_in[5];
    const float* Wv = (const float*)d_in[6];
    const float* Wo = (const float*)d_in[7];
    const float* Wg = (const float*)d_in[8];
    const int*   wl = (const int*)d_in[9];
    float* out = (float*)d_out;

    // Idempotent, host-side, not stream-ordered: safe under graph capture and
    // deterministic across calls (no static guards allowed).
    cudaFuncSetAttribute(attn, cudaFuncAttributeMaxDynamicSharedMemorySize,
                         SM_FLOATS * sizeof(float));

    // QKV projections -> g_qkv rows [q(1024) | k(256) | v(256)]
    gemm_tf32<<<dim3(8, 32), 256>>>(x, Wq, nullptr, 1024, QKROW, 0,    0, 0);
    gemm_tf32<<<dim3(2, 32), 256>>>(x, Wk, nullptr, 1024, QKROW, 1024, 0, 0);
    gemm_tf32<<<dim3(2, 32), 256>>>(x, Wv, nullptr, 1024, QKROW, 1280, 0, 0);

    // gate*ve add, rotary + rmsnorm * QK_SCALE
    postproc<<<MTOT, 768>>>(x, ve, cs, sn, Wg);

    // sliding-window flash attention (TF32 tensor cores) -> g_y
    attn<<<dim3(16, NHEAD, 2), 256, SM_FLOATS * sizeof(float)>>>(wl);

    // output projection: out = g_y @ Wo^T
    gemm_tf32<<<dim3(8, 32), 256>>>(nullptr, Wo, out, 1024, 1024, 0, 1, 1);
}

// round 9
// speedup vs baseline: 2.5299x; 1.2574x over previous
#include <cuda_runtime.h>
#include <cstdint>

#define TSEQ   2048
#define MTOT   4096          // B*T
#define QKROW  1536          // q(1024) | k(256) | v(256)
#define NHEAD  16
#define NKV    4
#define HD     64

// Scratch (no allocation allowed): qkv activations and attention output.
__device__ float g_qkv[(size_t)MTOT * QKROW];
__device__ float g_y[(size_t)MTOT * 1024];

__device__ __forceinline__ float tf32r(float x) {
    uint32_t u;
    asm("cvt.rna.tf32.f32 %0, %1;" : "=r"(u) : "f"(x));
    return __uint_as_float(u);
}

__device__ __forceinline__ void mma_tf32(float* d, const uint32_t* a, const uint32_t* b) {
    asm volatile(
        "mma.sync.aligned.m16n8k8.row.col.f32.tf32.tf32.f32 "
        "{%0,%1,%2,%3}, {%4,%5,%6,%7}, {%8,%9}, {%0,%1,%2,%3};\n"
        : "+f"(d[0]), "+f"(d[1]), "+f"(d[2]), "+f"(d[3])
        : "r"(a[0]), "r"(a[1]), "r"(a[2]), "r"(a[3]), "r"(b[0]), "r"(b[1]));
}

// ---------------------------------------------------------------------------
// Shared TF32 GEMM body: C[m][coff+n] = sum_k A[m][k] * B[n][k]
// Block 128x128, BK=32, 256 threads = 8 warps (2m x 4n), warp tile 64x32.
// Per-element math identical to the verified R7 kernel.
// ---------------------------------------------------------------------------
__device__ __forceinline__
void gemm_body(const float* __restrict__ A, const float* __restrict__ B,
               float* __restrict__ C, int K, int ldc, int coff, int bm)
{
    __shared__ float As[32][132];   // [k][m], padded
    __shared__ float Bs[32][132];   // [k][n], padded

    const int tid   = threadIdx.x;
    const int wid   = tid >> 5;
    const int lane  = tid & 31;
    const int group = lane >> 2;    // 0..7
    const int qid   = lane & 3;     // 0..3
    const int wm    = (wid >> 2) << 6;  // 0 or 64
    const int wn    = (wid & 3) << 5;   // 0,32,64,96

    float acc[4][4][4];
    #pragma unroll
    for (int mt = 0; mt < 4; mt++)
        #pragma unroll
        for (int nt = 0; nt < 4; nt++)
            #pragma unroll
            for (int r = 0; r < 4; r++) acc[mt][nt][r] = 0.f;

    for (int kt = 0; kt < K; kt += 32) {
        __syncthreads();
        #pragma unroll
        for (int it = 0; it < 4; it++) {
            const int idx = tid + (it << 8);
            const int r   = idx >> 3;          // 0..127
            const int c4  = (idx & 7) << 2;    // 0,4,...,28
            float4 av = *(const float4*)(A + (size_t)(bm + r) * K + kt + c4);
            float4 bv = *(const float4*)(B + (size_t)r * K + kt + c4);
            As[c4+0][r] = tf32r(av.x); As[c4+1][r] = tf32r(av.y);
            As[c4+2][r] = tf32r(av.z); As[c4+3][r] = tf32r(av.w);
            Bs[c4+0][r] = tf32r(bv.x); Bs[c4+1][r] = tf32r(bv.y);
            Bs[c4+2][r] = tf32r(bv.z); Bs[c4+3][r] = tf32r(bv.w);
        }
        __syncthreads();

        #pragma unroll
        for (int kk = 0; kk < 32; kk += 8) {
            uint32_t af[4][4], bf[4][2];
            #pragma unroll
            for (int mt = 0; mt < 4; mt++) {
                const int m0 = wm + (mt << 4) + group;
                af[mt][0] = __float_as_uint(As[kk + qid    ][m0]);
                af[mt][1] = __float_as_uint(As[kk + qid    ][m0 + 8]);
                af[mt][2] = __float_as_uint(As[kk + qid + 4][m0]);
                af[mt][3] = __float_as_uint(As[kk + qid + 4][m0 + 8]);
            }
            #pragma unroll
            for (int nt = 0; nt < 4; nt++) {
                const int n0 = wn + (nt << 3) + group;
                bf[nt][0] = __float_as_uint(Bs[kk + qid    ][n0]);
                bf[nt][1] = __float_as_uint(Bs[kk + qid + 4][n0]);
            }
            #pragma unroll
            for (int mt = 0; mt < 4; mt++)
                #pragma unroll
                for (int nt = 0; nt < 4; nt++)
                    mma_tf32(acc[mt][nt], af[mt], bf[nt]);
        }
    }

    #pragma unroll
    for (int mt = 0; mt < 4; mt++) {
        const int r0 = bm + wm + (mt << 4) + group;
        #pragma unroll
        for (int nt = 0; nt < 4; nt++) {
            const int c0 = coff + wn + (nt << 3) + (qid << 1);
            *(float2*)&C[(size_t)r0 * ldc + c0] =
                make_float2(acc[mt][nt][0], acc[mt][nt][1]);
            *(float2*)&C[(size_t)(r0 + 8) * ldc + c0] =
                make_float2(acc[mt][nt][2], acc[mt][nt][3]);
        }
    }
}

// Fused QKV projection: one launch, grid (12, 32). n-segment selects W.
__global__ __launch_bounds__(256)
void gemm_qkv(const float* __restrict__ x, const float* __restrict__ Wq,
              const float* __restrict__ Wk, const float* __restrict__ Wv)
{
    const int bn = blockIdx.x;          // 0..11  (global col = bn*128)
    const float* Bp; int nb;
    if (bn < 8)       { Bp = Wq; nb = bn; }
    else if (bn < 10) { Bp = Wk; nb = bn - 8; }
    else              { Bp = Wv; nb = bn - 10; }
    gemm_body(x, Bp + (size_t)(nb << 7) * 1024, g_qkv,
              1024, QKROW, bn << 7, blockIdx.y << 7);
}

// Output projection: out = g_y @ Wo^T, grid (8, 32).
__global__ __launch_bounds__(256)
void gemm_out(const float* __restrict__ Wo, float* __restrict__ out)
{
    gemm_body(g_y, Wo + (size_t)(blockIdx.x << 7) * 1024, out,
              1024, 1024, blockIdx.x << 7, blockIdx.y << 7);
}

// ---------------------------------------------------------------------------
// Post-process (rotary+rmsnorm on q/k, gated ve add on v). Unchanged.
// ---------------------------------------------------------------------------
__global__ __launch_bounds__(768)
void postproc(const float* __restrict__ x, const float* __restrict__ ve,
              const float* __restrict__ cs, const float* __restrict__ sn,
              const float* __restrict__ Wg)
{
    const int row = blockIdx.x;            // b*T + t
    const int t = row & (TSEQ - 1);
    const int w = threadIdx.x >> 5;
    const int l = threadIdx.x & 31;
    float* base = g_qkv + (size_t)row * QKROW;

    if (w < 20) {
        const int off = (w < 16) ? (w << 6) : (1024 + ((w - 16) << 6));
        float x1 = base[off + l];
        float x2 = base[off + 32 + l];
        float c = cs[t * 32 + l];
        float s = sn[t * 32 + l];
        float a  = x1 * c + x2 * s;
        float bb = x2 * c - x1 * s;
        float ss = a * a + bb * bb;
        #pragma unroll
        for (int d = 16; d >= 1; d >>= 1) ss += __shfl_xor_sync(0xffffffffu, ss, d);
        float r = rsqrtf(ss * (1.0f / 64.0f) + 1.1920929e-7f) * 1.2f;
        base[off + l]      = a  * r;
        base[off + 32 + l] = bb * r;
    } else {
        const int kv = w - 20;
        float dot = (l < 12) ? x[(size_t)row * 1024 + l] * Wg[kv * 12 + l] : 0.f;
        #pragma unroll
        for (int d = 16; d >= 1; d >>= 1) dot += __shfl_xor_sync(0xffffffffu, dot, d);
        float g = 3.0f / (1.0f + __expf(-dot));
        const int off = 1280 + (kv << 6);
        const float* vep = ve + (size_t)row * 256 + (kv << 6);
        base[off + l]      += g * vep[l];
        base[off + 32 + l] += g * vep[32 + l];
    }
}

// ---------------------------------------------------------------------------
// Flash attention on TF32 tensor cores. Restructured vs R7 (same numerics):
//  - Q fragments hoisted to registers (loaded once per block)
//  - P buffer ALIASES the Q smem region (warp-private rows, no block sync)
//  - K/V double-buffered: one __syncthreads per tile, loads for tile t+1
//    issued after compute of tile t (inter-warp overlap)
// smem (dynamic, 106496 B): QP[128][68] | K0[64][68] V0[64][72] | K1 V1
// ---------------------------------------------------------------------------
#define PADQ 68
#define PADK 68
#define PADV 72
#define OK0 (128 * PADQ)
#define OV0 (OK0 + 64 * PADK)
#define OK1 (OV0 + 64 * PADV)
#define OV1 (OK1 + 64 * PADK)
#define SM_FLOATS (OV1 + 64 * PADV)

__device__ __forceinline__
void load_kv_tile(const float* __restrict__ kptr, const float* __restrict__ vptr,
                  int k0, int tid, float* __restrict__ kd_base,
                  float* __restrict__ vd_base)
{
    const int r  = tid >> 2;
    const int c0 = (tid & 3) << 4;
    const float* ks = kptr + (size_t)(k0 + r) * QKROW + c0;
    const float* vs = vptr + (size_t)(k0 + r) * QKROW + c0;
    float* kd = kd_base + r * PADK + c0;
    float* vd = vd_base + r * PADV + c0;
    #pragma unroll
    for (int i = 0; i < 16; i += 4) {
        float4 k4 = *(const float4*)(ks + i);
        float4 v4 = *(const float4*)(vs + i);
        kd[i+0] = tf32r(k4.x); kd[i+1] = tf32r(k4.y);
        kd[i+2] = tf32r(k4.z); kd[i+3] = tf32r(k4.w);
        vd[i+0] = tf32r(v4.x); vd[i+1] = tf32r(v4.y);
        vd[i+2] = tf32r(v4.z); vd[i+3] = tf32r(v4.w);
    }
}

__global__ __launch_bounds__(256, 2)
void attn(const int* __restrict__ wlp)
{
    extern __shared__ float sm[];
    float* QP = sm;                 // Q tile, then P (exp scores)

    const int tid  = threadIdx.x;
    const int w    = tid >> 5;
    const int lane = tid & 31;
    const int g    = lane >> 2;
    const int qid  = lane & 3;
    const int qt = blockIdx.x;      // 0..15
    const int h  = blockIdx.y;      // 0..15
    const int b  = blockIdx.z;      // 0..1
    const int window = *wlp;
    const int kv = h >> 2;
    const int q0 = qt << 7;

    const float* rowbase = g_qkv + (size_t)b * TSEQ * QKROW;
    const float* qptr = rowbase + h * 64;
    const float* kptr = rowbase + 1024 + kv * 64;
    const float* vptr = rowbase + 1280 + kv * 64;

    {   // load Q tile (warp w loads exactly its own rows 16w..16w+15)
        const int r = tid >> 1;
        const int c0 = (tid & 1) << 5;
        const float* src = qptr + (size_t)(q0 + r) * QKROW + c0;
        float* dst = QP + r * PADQ + c0;
        #pragma unroll
        for (int i = 0; i < 32; i += 4) {
            float4 v4 = *(const float4*)(src + i);
            dst[i+0] = tf32r(v4.x); dst[i+1] = tf32r(v4.y);
            dst[i+2] = tf32r(v4.z); dst[i+3] = tf32r(v4.w);
        }
    }
    __syncwarp();

    const int mrow = (w << 4) + g;
    const int qlo = q0 + mrow;
    const int qhi = qlo + 8;

    // Hoist Q fragments to registers (loop-invariant); QP then freed for P.
    uint32_t qf[8][4];
    #pragma unroll
    for (int k8 = 0; k8 < 8; k8++) {
        qf[k8][0] = __float_as_uint(QP[(mrow    ) * PADQ + (k8 << 3) + qid]);
        qf[k8][1] = __float_as_uint(QP[(mrow + 8) * PADQ + (k8 << 3) + qid]);
        qf[k8][2] = __float_as_uint(QP[(mrow    ) * PADQ + (k8 << 3) + qid + 4]);
        qf[k8][3] = __float_as_uint(QP[(mrow + 8) * PADQ + (k8 << 3) + qid + 4]);
    }
    __syncwarp();

    float o[8][4];
    #pragma unroll
    for (int nt = 0; nt < 8; nt++)
        #pragma unroll
        for (int r = 0; r < 4; r++) o[nt][r] = 0.f;
    float m_lo = -1e30f, m_hi = -1e30f, l_lo = 0.f, l_hi = 0.f;

    int lo = q0 - window; if (lo < 0) lo = 0;
    const int kt0 = lo >> 6;
    const int ktmax = (q0 + 127) >> 6;

    // preload first K/V tile into buffer 0
    load_kv_tile(kptr, vptr, kt0 << 6, tid, sm + OK0, sm + OV0);
    __syncthreads();
    int p = 0;

    for (int kt = kt0; kt <= ktmax; kt++) {
        const int k0 = kt << 6;
        const float* Kc = sm + (p ? OK1 : OK0);
        const float* Vc = sm + (p ? OV1 : OV0);

        // ---- S = Q K^T (16 x 64 per warp) ----
        float s[8][4];
        #pragma unroll
        for (int nt = 0; nt < 8; nt++)
            #pragma unroll
            for (int r = 0; r < 4; r++) s[nt][r] = 0.f;
        #pragma unroll
        for (int k8 = 0; k8 < 8; k8++) {
            const int kk = k8 << 3;
            #pragma unroll
            for (int nt = 0; nt < 8; nt++) {
                uint32_t bfr[2];
                bfr[0] = __float_as_uint(Kc[((nt << 3) + g) * PADK + kk + qid]);
                bfr[1] = __float_as_uint(Kc[((nt << 3) + g) * PADK + kk + qid + 4]);
                mma_tf32(s[nt], qf[k8], bfr);
            }
        }

        // ---- mask + online softmax (warp-local rows) ----
        const bool interior = (k0 + 63 <= q0) && (q0 + 127 - k0 <= window);
        float rx_lo = -1e30f, rx_hi = -1e30f;
        if (interior) {
            #pragma unroll
            for (int nt = 0; nt < 8; nt++) {
                #pragma unroll
                for (int c = 0; c < 2; c++) {
                    s[nt][c]     *= 0.125f;
                    s[nt][2 + c] *= 0.125f;
                    rx_lo = fmaxf(rx_lo, s[nt][c]);
                    rx_hi = fmaxf(rx_hi, s[nt][2 + c]);
                }
            }
        } else {
            #pragma unroll
            for (int nt = 0; nt < 8; nt++) {
                #pragma unroll
                for (int c = 0; c < 2; c++) {
                    const int kj = k0 + (nt << 3) + (qid << 1) + c;
                    const bool ok_lo = (kj <= qlo) && (qlo - kj <= window);
                    const bool ok_hi = (kj <= qhi) && (qhi - kj <= window);
                    s[nt][c]     = ok_lo ? s[nt][c]     * 0.125f : -1e30f;
                    s[nt][2 + c] = ok_hi ? s[nt][2 + c] * 0.125f : -1e30f;
                    rx_lo = fmaxf(rx_lo, s[nt][c]);
                    rx_hi = fmaxf(rx_hi, s[nt][2 + c]);
                }
            }
        }
        rx_lo = fmaxf(rx_lo, __shfl_xor_sync(0xffffffffu, rx_lo, 1));
        rx_lo = fmaxf(rx_lo, __shfl_xor_sync(0xffffffffu, rx_lo, 2));
        rx_hi = fmaxf(rx_hi, __shfl_xor_sync(0xffffffffu, rx_hi, 1));
        rx_hi = fmaxf(rx_hi, __shfl_xor_sync(0xffffffffu, rx_hi, 2));

        const float mn_lo = fmaxf(m_lo, rx_lo);
        const float mn_hi = fmaxf(m_hi, rx_hi);
        const float cr_lo = __expf(m_lo - mn_lo);
        const float cr_hi = __expf(m_hi - mn_hi);
        float rs_lo = 0.f, rs_hi = 0.f;
        #pragma unroll
        for (int nt = 0; nt < 8; nt++) {
            float e0 = __expf(s[nt][0] - mn_lo);
            float e1 = __expf(s[nt][1] - mn_lo);
            float e2 = __expf(s[nt][2] - mn_hi);
            float e3 = __expf(s[nt][3] - mn_hi);
            rs_lo += e0 + e1;
            rs_hi += e2 + e3;
            const int pc = (nt << 3) + (qid << 1);
            *(float2*)&QP[(mrow    ) * PADQ + pc] = make_float2(tf32r(e0), tf32r(e1));
            *(float2*)&QP[(mrow + 8) * PADQ + pc] = make_float2(tf32r(e2), tf32r(e3));
        }
        rs_lo += __shfl_xor_sync(0xffffffffu, rs_lo, 1);
        rs_lo += __shfl_xor_sync(0xffffffffu, rs_lo, 2);
        rs_hi += __shfl_xor_sync(0xffffffffu, rs_hi, 1);
        rs_hi += __shfl_xor_sync(0xffffffffu, rs_hi, 2);
        m_lo = mn_lo; m_hi = mn_hi;
        l_lo = l_lo * cr_lo + rs_lo;
        l_hi = l_hi * cr_hi + rs_hi;
        #pragma unroll
        for (int nt = 0; nt < 8; nt++) {
            o[nt][0] *= cr_lo; o[nt][1] *= cr_lo;
            o[nt][2] *= cr_hi; o[nt][3] *= cr_hi;
        }
        __syncwarp();   // P rows visible across own warp's lanes

        // ---- O += P V (16 x 64 per warp) ----
        #pragma unroll
        for (int k8 = 0; k8 < 8; k8++) {
            const int kk = k8 << 3;
            uint32_t a[4];
            a[0] = __float_as_uint(QP[(mrow    ) * PADQ + kk + qid]);
            a[1] = __float_as_uint(QP[(mrow + 8) * PADQ + kk + qid]);
            a[2] = __float_as_uint(QP[(mrow    ) * PADQ + kk + qid + 4]);
            a[3] = __float_as_uint(QP[(mrow + 8) * PADQ + kk + qid + 4]);
            #pragma unroll
            for (int nt = 0; nt < 8; nt++) {
                uint32_t bfr[2];
                bfr[0] = __float_as_uint(Vc[(kk + qid    ) * PADV + (nt << 3) + g]);
                bfr[1] = __float_as_uint(Vc[(kk + qid + 4) * PADV + (nt << 3) + g]);
                mma_tf32(o[nt], a, bfr);
            }
        }
        __syncwarp();   // PV reads done before next tile's P overwrite

        // ---- prefetch next K/V tile into the other buffer ----
        if (kt < ktmax)
            load_kv_tile(kptr, vptr, (kt + 1) << 6, tid,
                         sm + (p ? OK0 : OK1), sm + (p ? OV0 : OV1));
        __syncthreads();
        p ^= 1;
    }

    const float inv_lo = 1.0f / l_lo;
    const float inv_hi = 1.0f / l_hi;
    float* ylo = g_y + (size_t)(b * TSEQ + qlo) * 1024 + h * 64;
    float* yhi = g_y + (size_t)(b * TSEQ + qhi) * 1024 + h * 64;
    #pragma unroll
    for (int nt = 0; nt < 8; nt++) {
        const int c = (nt << 3) + (qid << 1);
        *(float2*)(ylo + c) = make_float2(o[nt][0] * inv_lo, o[nt][1] * inv_lo);
        *(float2*)(yhi + c) = make_float2(o[nt][2] * inv_hi, o[nt][3] * inv_hi);
    }
}

// ---------------------------------------------------------------------------
extern "C" void kernel_launch(void* const* d_in, const int* in_sizes, int n_in,
                              void* d_out, int out_size)
{
    const float* x  = (const float*)d_in[0];
    const float* ve = (const float*)d_in[1];
    const float* cs = (const float*)d_in[2];
    const float* sn = (const float*)d_in[3];
    const float* Wq = (const float*)d_in[4];
    const float* Wk = (const float*)d_in[5];
    const float* Wv = (const float*)d_in[6];
    const float* Wo = (const float*)d_in[7];
    const float* Wg = (const float*)d_in[8];
    const int*   wl = (const int*)d_in[9];
    float* out = (float*)d_out;

    // Idempotent host-side call; safe under graph capture, no static guards.
    cudaFuncSetAttribute(attn, cudaFuncAttributeMaxDynamicSharedMemorySize,
                         SM_FLOATS * sizeof(float));

    // Fused QKV projection -> g_qkv rows [q(1024) | k(256) | v(256)]
    gemm_qkv<<<dim3(12, 32), 256>>>(x, Wq, Wk, Wv);

    // gate*ve add, rotary + rmsnorm * QK_SCALE
    postproc<<<MTOT, 768>>>(x, ve, cs, sn, Wg);

    // sliding-window flash attention (TF32 tensor cores) -> g_y
    attn<<<dim3(16, NHEAD, 2), 256, SM_FLOATS * sizeof(float)>>>(wl);

    // output projection: out = g_y @ Wo^T
    gemm_out<<<dim3(8, 32), 256>>>(Wo, out);
}

// round 11
// speedup vs baseline: 3.0226x; 1.1947x over previous
#include <cuda_runtime.h>
#include <cstdint>

#define TSEQ   2048
#define MTOT   4096          // B*T
#define QKROW  1536          // q(1024) | k(256) | v(256)
#define NHEAD  16
#define NKV    4
#define HD     64

// Scratch (no allocation allowed): qkv activations and attention output.
__device__ float g_qkv[(size_t)MTOT * QKROW];
__device__ float g_y[(size_t)MTOT * 1024];

__device__ __forceinline__ float tf32r(float x) {
    uint32_t u;
    asm("cvt.rna.tf32.f32 %0, %1;" : "=r"(u) : "f"(x));
    return __uint_as_float(u);
}
__device__ __forceinline__ uint32_t tf32u(float x) {
    uint32_t u;
    asm("cvt.rna.tf32.f32 %0, %1;" : "=r"(u) : "f"(x));
    return u;
}

__device__ __forceinline__ void mma_tf32(float* d, const uint32_t* a, const uint32_t* b) {
    asm volatile(
        "mma.sync.aligned.m16n8k8.row.col.f32.tf32.tf32.f32 "
        "{%0,%1,%2,%3}, {%4,%5,%6,%7}, {%8,%9}, {%0,%1,%2,%3};\n"
        : "+f"(d[0]), "+f"(d[1]), "+f"(d[2]), "+f"(d[3])
        : "r"(a[0]), "r"(a[1]), "r"(a[2]), "r"(a[3]), "r"(b[0]), "r"(b[1]));
}

__device__ __forceinline__ void cpa16(float* dst, const float* src) {
    uint32_t s = (uint32_t)__cvta_generic_to_shared(dst);
    asm volatile("cp.async.cg.shared.global [%0], [%1], 16;\n" :: "r"(s), "l"(src));
}
__device__ __forceinline__ void cpa_commit() { asm volatile("cp.async.commit_group;\n"); }
__device__ __forceinline__ void cpa_wait0()  { asm volatile("cp.async.wait_group 0;\n" ::: "memory"); }

// ---------------------------------------------------------------------------
// TF32 GEMM, 128x256 block tile, BK=32, 256 threads = 8 warps (2m x 4n),
// warp tile 64x64 (4 mt x 8 nt m16n8k8). cp.async double-buffered mainloop;
// fp32 stored raw in smem, tf32 rounding applied at fragment load (identical
// rounded values to the verified R7/R9 kernels -> numerics bit-identical).
// smem per stage: A[128][36] + B[256][36]; two stages = 110592 B dynamic.
// ---------------------------------------------------------------------------
#define ASTRIDE 36
#define ABUF (128 * ASTRIDE)
#define BBUF (256 * ASTRIDE)
#define GBUF (ABUF + BBUF)
#define GSM_BYTES (2 * GBUF * 4)

__device__ __forceinline__
void gemm_body(const float* __restrict__ A, const float* __restrict__ B,
               float* __restrict__ C, int K, int ldc, int coff, int bm,
               float* __restrict__ sm)
{
    const int tid  = threadIdx.x;
    const int wid  = tid >> 5;
    const int lane = tid & 31;
    const int g    = lane >> 2;
    const int qid  = lane & 3;
    const int wm   = (wid >> 2) << 6;   // 0 or 64
    const int wn   = (wid & 3) << 6;    // 0,64,128,192

    float acc[4][8][4];
    #pragma unroll
    for (int mt = 0; mt < 4; mt++)
        #pragma unroll
        for (int nt = 0; nt < 8; nt++)
            #pragma unroll
            for (int r = 0; r < 4; r++) acc[mt][nt][r] = 0.f;

    const int KT = K >> 5;

    auto issue = [&](int kt, float* buf) {
        const float* Ag = A + (size_t)bm * K + (kt << 5);
        #pragma unroll
        for (int it = 0; it < 4; it++) {
            const int ca = tid + (it << 8);
            const int r = ca >> 3, ck = (ca & 7) << 2;
            cpa16(buf + r * ASTRIDE + ck, Ag + (size_t)r * K + ck);
        }
        const float* Bg = B + (kt << 5);
        float* bb = buf + ABUF;
        #pragma unroll
        for (int it = 0; it < 8; it++) {
            const int cb = tid + (it << 8);
            const int r = cb >> 3, ck = (cb & 7) << 2;
            cpa16(bb + r * ASTRIDE + ck, Bg + (size_t)r * K + ck);
        }
        cpa_commit();
    };

    issue(0, sm);
    for (int kt = 0; kt < KT; kt++) {
        cpa_wait0();
        __syncthreads();    // tile kt resident; all warps done with this stage's previous occupant
        if (kt + 1 < KT) issue(kt + 1, sm + ((kt + 1) & 1) * GBUF);

        const float* As = sm + (kt & 1) * GBUF;
        const float* Bs = As + ABUF;

        #pragma unroll
        for (int kk = 0; kk < 32; kk += 8) {
            uint32_t af[4][4], bf[8][2];
            #pragma unroll
            for (int mt = 0; mt < 4; mt++) {
                const int m0 = wm + (mt << 4) + g;
                af[mt][0] = tf32u(As[(m0    ) * ASTRIDE + kk + qid]);
                af[mt][1] = tf32u(As[(m0 + 8) * ASTRIDE + kk + qid]);
                af[mt][2] = tf32u(As[(m0    ) * ASTRIDE + kk + qid + 4]);
                af[mt][3] = tf32u(As[(m0 + 8) * ASTRIDE + kk + qid + 4]);
            }
            #pragma unroll
            for (int nt = 0; nt < 8; nt++) {
                const int n0 = wn + (nt << 3) + g;
                bf[nt][0] = tf32u(Bs[n0 * ASTRIDE + kk + qid]);
                bf[nt][1] = tf32u(Bs[n0 * ASTRIDE + kk + qid + 4]);
            }
            #pragma unroll
            for (int mt = 0; mt < 4; mt++)
                #pragma unroll
                for (int nt = 0; nt < 8; nt++)
                    mma_tf32(acc[mt][nt], af[mt], bf[nt]);
        }
    }

    #pragma unroll
    for (int mt = 0; mt < 4; mt++) {
        const int r0 = bm + wm + (mt << 4) + g;
        #pragma unroll
        for (int nt = 0; nt < 8; nt++) {
            const int c0 = coff + wn + (nt << 3) + (qid << 1);
            *(float2*)&C[(size_t)r0 * ldc + c0] =
                make_float2(acc[mt][nt][0], acc[mt][nt][1]);
            *(float2*)&C[(size_t)(r0 + 8) * ldc + c0] =
                make_float2(acc[mt][nt][2], acc[mt][nt][3]);
        }
    }
}

// Fused QKV projection: grid (6, 32). 256-col block selects W segment.
__global__ __launch_bounds__(256, 1)
void gemm_qkv(const float* __restrict__ x, const float* __restrict__ Wq,
              const float* __restrict__ Wk, const float* __restrict__ Wv)
{
    extern __shared__ float gsm[];
    const int bx = blockIdx.x;          // 0..5, global col = bx*256
    const float* Bp;
    if (bx < 4)      Bp = Wq + (size_t)(bx << 8) * 1024;
    else if (bx == 4) Bp = Wk;
    else              Bp = Wv;
    gemm_body(x, Bp, g_qkv, 1024, QKROW, bx << 8, blockIdx.y << 7, gsm);
}

// Output projection: out = g_y @ Wo^T, grid (4, 32).
__global__ __launch_bounds__(256, 1)
void gemm_out(const float* __restrict__ Wo, float* __restrict__ out)
{
    extern __shared__ float gsm[];
    gemm_body(g_y, Wo + (size_t)(blockIdx.x << 8) * 1024, out,
              1024, 1024, blockIdx.x << 8, blockIdx.y << 7, gsm);
}

// ---------------------------------------------------------------------------
// Post-process (rotary+rmsnorm on q/k, gated ve add on v). Unchanged.
// ---------------------------------------------------------------------------
__global__ __launch_bounds__(768)
void postproc(const float* __restrict__ x, const float* __restrict__ ve,
              const float* __restrict__ cs, const float* __restrict__ sn,
              const float* __restrict__ Wg)
{
    const int row = blockIdx.x;            // b*T + t
    const int t = row & (TSEQ - 1);
    const int w = threadIdx.x >> 5;
    const int l = threadIdx.x & 31;
    float* base = g_qkv + (size_t)row * QKROW;

    if (w < 20) {
        const int off = (w < 16) ? (w << 6) : (1024 + ((w - 16) << 6));
        float x1 = base[off + l];
        float x2 = base[off + 32 + l];
        float c = cs[t * 32 + l];
        float s = sn[t * 32 + l];
        float a  = x1 * c + x2 * s;
        float bb = x2 * c - x1 * s;
        float ss = a * a + bb * bb;
        #pragma unroll
        for (int d = 16; d >= 1; d >>= 1) ss += __shfl_xor_sync(0xffffffffu, ss, d);
        float r = rsqrtf(ss * (1.0f / 64.0f) + 1.1920929e-7f) * 1.2f;
        base[off + l]      = a  * r;
        base[off + 32 + l] = bb * r;
    } else {
        const int kv = w - 20;
        float dot = (l < 12) ? x[(size_t)row * 1024 + l] * Wg[kv * 12 + l] : 0.f;
        #pragma unroll
        for (int d = 16; d >= 1; d >>= 1) dot += __shfl_xor_sync(0xffffffffu, dot, d);
        float g = 3.0f / (1.0f + __expf(-dot));
        const int off = 1280 + (kv << 6);
        const float* vep = ve + (size_t)row * 256 + (kv << 6);
        base[off + l]      += g * vep[l];
        base[off + 32 + l] += g * vep[32 + l];
    }
}

// ---------------------------------------------------------------------------
// Flash attention on TF32 tensor cores (verified R9 version, unchanged).
// ---------------------------------------------------------------------------
#define PADQ 68
#define PADK 68
#define PADV 72
#define OK0 (128 * PADQ)
#define OV0 (OK0 + 64 * PADK)
#define OK1 (OV0 + 64 * PADV)
#define OV1 (OK1 + 64 * PADK)
#define SM_FLOATS (OV1 + 64 * PADV)

__device__ __forceinline__
void load_kv_tile(const float* __restrict__ kptr, const float* __restrict__ vptr,
                  int k0, int tid, float* __restrict__ kd_base,
                  float* __restrict__ vd_base)
{
    const int r  = tid >> 2;
    const int c0 = (tid & 3) << 4;
    const float* ks = kptr + (size_t)(k0 + r) * QKROW + c0;
    const float* vs = vptr + (size_t)(k0 + r) * QKROW + c0;
    float* kd = kd_base + r * PADK + c0;
    float* vd = vd_base + r * PADV + c0;
    #pragma unroll
    for (int i = 0; i < 16; i += 4) {
        float4 k4 = *(const float4*)(ks + i);
        float4 v4 = *(const float4*)(vs + i);
        kd[i+0] = tf32r(k4.x); kd[i+1] = tf32r(k4.y);
        kd[i+2] = tf32r(k4.z); kd[i+3] = tf32r(k4.w);
        vd[i+0] = tf32r(v4.x); vd[i+1] = tf32r(v4.y);
        vd[i+2] = tf32r(v4.z); vd[i+3] = tf32r(v4.w);
    }
}

__global__ __launch_bounds__(256, 2)
void attn(const int* __restrict__ wlp)
{
    extern __shared__ float sm[];
    float* QP = sm;                 // Q tile, then P (exp scores)

    const int tid  = threadIdx.x;
    const int w    = tid >> 5;
    const int lane = tid & 31;
    const int g    = lane >> 2;
    const int qid  = lane & 3;
    const int qt = blockIdx.x;      // 0..15
    const int h  = blockIdx.y;      // 0..15
    const int b  = blockIdx.z;      // 0..1
    const int window = *wlp;
    const int kv = h >> 2;
    const int q0 = qt << 7;

    const float* rowbase = g_qkv + (size_t)b * TSEQ * QKROW;
    const float* qptr = rowbase + h * 64;
    const float* kptr = rowbase + 1024 + kv * 64;
    const float* vptr = rowbase + 1280 + kv * 64;

    {   // load Q tile (warp w loads exactly its own rows 16w..16w+15)
        const int r = tid >> 1;
        const int c0 = (tid & 1) << 5;
        const float* src = qptr + (size_t)(q0 + r) * QKROW + c0;
        float* dst = QP + r * PADQ + c0;
        #pragma unroll
        for (int i = 0; i < 32; i += 4) {
            float4 v4 = *(const float4*)(src + i);
            dst[i+0] = tf32r(v4.x); dst[i+1] = tf32r(v4.y);
            dst[i+2] = tf32r(v4.z); dst[i+3] = tf32r(v4.w);
        }
    }
    __syncwarp();

    const int mrow = (w << 4) + g;
    const int qlo = q0 + mrow;
    const int qhi = qlo + 8;

    uint32_t qf[8][4];
    #pragma unroll
    for (int k8 = 0; k8 < 8; k8++) {
        qf[k8][0] = __float_as_uint(QP[(mrow    ) * PADQ + (k8 << 3) + qid]);
        qf[k8][1] = __float_as_uint(QP[(mrow + 8) * PADQ + (k8 << 3) + qid]);
        qf[k8][2] = __float_as_uint(QP[(mrow    ) * PADQ + (k8 << 3) + qid + 4]);
        qf[k8][3] = __float_as_uint(QP[(mrow + 8) * PADQ + (k8 << 3) + qid + 4]);
    }
    __syncwarp();

    float o[8][4];
    #pragma unroll
    for (int nt = 0; nt < 8; nt++)
        #pragma unroll
        for (int r = 0; r < 4; r++) o[nt][r] = 0.f;
    float m_lo = -1e30f, m_hi = -1e30f, l_lo = 0.f, l_hi = 0.f;

    int lo = q0 - window; if (lo < 0) lo = 0;
    const int kt0 = lo >> 6;
    const int ktmax = (q0 + 127) >> 6;

    load_kv_tile(kptr, vptr, kt0 << 6, tid, sm + OK0, sm + OV0);
    __syncthreads();
    int p = 0;

    for (int kt = kt0; kt <= ktmax; kt++) {
        const int k0 = kt << 6;
        const float* Kc = sm + (p ? OK1 : OK0);
        const float* Vc = sm + (p ? OV1 : OV0);

        float s[8][4];
        #pragma unroll
        for (int nt = 0; nt < 8; nt++)
            #pragma unroll
            for (int r = 0; r < 4; r++) s[nt][r] = 0.f;
        #pragma unroll
        for (int k8 = 0; k8 < 8; k8++) {
            const int kk = k8 << 3;
            #pragma unroll
            for (int nt = 0; nt < 8; nt++) {
                uint32_t bfr[2];
                bfr[0] = __float_as_uint(Kc[((nt << 3) + g) * PADK + kk + qid]);
                bfr[1] = __float_as_uint(Kc[((nt << 3) + g) * PADK + kk + qid + 4]);
                mma_tf32(s[nt], qf[k8], bfr);
            }
        }

        const bool interior = (k0 + 63 <= q0) && (q0 + 127 - k0 <= window);
        float rx_lo = -1e30f, rx_hi = -1e30f;
        if (interior) {
            #pragma unroll
            for (int nt = 0; nt < 8; nt++) {
                #pragma unroll
                for (int c = 0; c < 2; c++) {
                    s[nt][c]     *= 0.125f;
                    s[nt][2 + c] *= 0.125f;
                    rx_lo = fmaxf(rx_lo, s[nt][c]);
                    rx_hi = fmaxf(rx_hi, s[nt][2 + c]);
                }
            }
        } else {
            #pragma unroll
            for (int nt = 0; nt < 8; nt++) {
                #pragma unroll
                for (int c = 0; c < 2; c++) {
                    const int kj = k0 + (nt << 3) + (qid << 1) + c;
                    const bool ok_lo = (kj <= qlo) && (qlo - kj <= window);
                    const bool ok_hi = (kj <= qhi) && (qhi - kj <= window);
                    s[nt][c]     = ok_lo ? s[nt][c]     * 0.125f : -1e30f;
                    s[nt][2 + c] = ok_hi ? s[nt][2 + c] * 0.125f : -1e30f;
                    rx_lo = fmaxf(rx_lo, s[nt][c]);
                    rx_hi = fmaxf(rx_hi, s[nt][2 + c]);
                }
            }
        }
        rx_lo = fmaxf(rx_lo, __shfl_xor_sync(0xffffffffu, rx_lo, 1));
        rx_lo = fmaxf(rx_lo, __shfl_xor_sync(0xffffffffu, rx_lo, 2));
        rx_hi = fmaxf(rx_hi, __shfl_xor_sync(0xffffffffu, rx_hi, 1));
        rx_hi = fmaxf(rx_hi, __shfl_xor_sync(0xffffffffu, rx_hi, 2));

        const float mn_lo = fmaxf(m_lo, rx_lo);
        const float mn_hi = fmaxf(m_hi, rx_hi);
        const float cr_lo = __expf(m_lo - mn_lo);
        const float cr_hi = __expf(m_hi - mn_hi);
        float rs_lo = 0.f, rs_hi = 0.f;
        #pragma unroll
        for (int nt = 0; nt < 8; nt++) {
            float e0 = __expf(s[nt][0] - mn_lo);
            float e1 = __expf(s[nt][1] - mn_lo);
            float e2 = __expf(s[nt][2] - mn_hi);
            float e3 = __expf(s[nt][3] - mn_hi);
            rs_lo += e0 + e1;
            rs_hi += e2 + e3;
            const int pc = (nt << 3) + (qid << 1);
            *(float2*)&QP[(mrow    ) * PADQ + pc] = make_float2(tf32r(e0), tf32r(e1));
            *(float2*)&QP[(mrow + 8) * PADQ + pc] = make_float2(tf32r(e2), tf32r(e3));
        }
        rs_lo += __shfl_xor_sync(0xffffffffu, rs_lo, 1);
        rs_lo += __shfl_xor_sync(0xffffffffu, rs_lo, 2);
        rs_hi += __shfl_xor_sync(0xffffffffu, rs_hi, 1);
        rs_hi += __shfl_xor_sync(0xffffffffu, rs_hi, 2);
        m_lo = mn_lo; m_hi = mn_hi;
        l_lo = l_lo * cr_lo + rs_lo;
        l_hi = l_hi * cr_hi + rs_hi;
        #pragma unroll
        for (int nt = 0; nt < 8; nt++) {
            o[nt][0] *= cr_lo; o[nt][1] *= cr_lo;
            o[nt][2] *= cr_hi; o[nt][3] *= cr_hi;
        }
        __syncwarp();

        #pragma unroll
        for (int k8 = 0; k8 < 8; k8++) {
            const int kk = k8 << 3;
            uint32_t a[4];
            a[0] = __float_as_uint(QP[(mrow    ) * PADQ + kk + qid]);
            a[1] = __float_as_uint(QP[(mrow + 8) * PADQ + kk + qid]);
            a[2] = __float_as_uint(QP[(mrow    ) * PADQ + kk + qid + 4]);
            a[3] = __float_as_uint(QP[(mrow + 8) * PADQ + kk + qid + 4]);
            #pragma unroll
            for (int nt = 0; nt < 8; nt++) {
                uint32_t bfr[2];
                bfr[0] = __float_as_uint(Vc[(kk + qid    ) * PADV + (nt << 3) + g]);
                bfr[1] = __float_as_uint(Vc[(kk + qid + 4) * PADV + (nt << 3) + g]);
                mma_tf32(o[nt], a, bfr);
            }
        }
        __syncwarp();

        if (kt < ktmax)
            load_kv_tile(kptr, vptr, (kt + 1) << 6, tid,
                         sm + (p ? OK0 : OK1), sm + (p ? OV0 : OV1));
        __syncthreads();
        p ^= 1;
    }

    const float inv_lo = 1.0f / l_lo;
    const float inv_hi = 1.0f / l_hi;
    float* ylo = g_y + (size_t)(b * TSEQ + qlo) * 1024 + h * 64;
    float* yhi = g_y + (size_t)(b * TSEQ + qhi) * 1024 + h * 64;
    #pragma unroll
    for (int nt = 0; nt < 8; nt++) {
        const int c = (nt << 3) + (qid << 1);
        *(float2*)(ylo + c) = make_float2(o[nt][0] * inv_lo, o[nt][1] * inv_lo);
        *(float2*)(yhi + c) = make_float2(o[nt][2] * inv_hi, o[nt][3] * inv_hi);
    }
}

// ---------------------------------------------------------------------------
extern "C" void kernel_launch(void* const* d_in, const int* in_sizes, int n_in,
                              void* d_out, int out_size)
{
    const float* x  = (const float*)d_in[0];
    const float* ve = (const float*)d_in[1];
    const float* cs = (const float*)d_in[2];
    const float* sn = (const float*)d_in[3];
    const float* Wq = (const float*)d_in[4];
    const float* Wk = (const float*)d_in[5];
    const float* Wv = (const float*)d_in[6];
    const float* Wo = (const float*)d_in[7];
    const float* Wg = (const float*)d_in[8];
    const int*   wl = (const int*)d_in[9];
    float* out = (float*)d_out;

    // Idempotent host-side calls; safe under graph capture, no static guards.
    cudaFuncSetAttribute(attn, cudaFuncAttributeMaxDynamicSharedMemorySize,
                         SM_FLOATS * sizeof(float));
    cudaFuncSetAttribute(gemm_qkv, cudaFuncAttributeMaxDynamicSharedMemorySize,
                         GSM_BYTES);
    cudaFuncSetAttribute(gemm_out, cudaFuncAttributeMaxDynamicSharedMemorySize,
                         GSM_BYTES);

    // Fused QKV projection -> g_qkv rows [q(1024) | k(256) | v(256)]
    gemm_qkv<<<dim3(6, 32), 256, GSM_BYTES>>>(x, Wq, Wk, Wv);

    // gate*ve add, rotary + rmsnorm * QK_SCALE
    postproc<<<MTOT, 768>>>(x, ve, cs, sn, Wg);

    // sliding-window flash attention (TF32 tensor cores) -> g_y
    attn<<<dim3(16, NHEAD, 2), 256, SM_FLOATS * sizeof(float)>>>(wl);

    // output projection: out = g_y @ Wo^T
    gemm_out<<<dim3(4, 32), 256, GSM_BYTES>>>(Wo, out);
}